// round 2
// baseline (speedup 1.0000x reference)
#include <cuda_runtime.h>

#define NN   50000
#define EE   800000
#define HIDD 128
#define EP   (EE + NN)     // 850000 edges incl. self-loops
#define OUTD 4

// ---------------- scratch (static device globals; no runtime allocation) ----
__device__ float    g_hA[(size_t)NN * HIDD];   // transformed features (gather source)
__device__ float    g_hB[(size_t)NN * HIDD];   // aggregated output
__device__ float    g_L[NN];
__device__ float    g_R[NN];
__device__ float    g_alpha[EP];               // alpha, then overwritten by exp(alpha-max)
__device__ unsigned g_amax[NN];                // order-preserving uint encoding of float max
__device__ float    g_denom[NN];
__device__ float    g_P[NN * OUTD];
__device__ float    g_Q[NN * OUTD];

// order-preserving float<->uint mapping (works for negatives / -inf)
__device__ __forceinline__ unsigned f2o(float f) {
    unsigned u = __float_as_uint(f);
    return (u & 0x80000000u) ? ~u : (u | 0x80000000u);
}
__device__ __forceinline__ float o2f(unsigned u) {
    return __uint_as_float((u & 0x80000000u) ? (u & 0x7FFFFFFFu) : ~u);
}
#define AMAX_INIT 0x007FFFFFu   // f2o(-inf)

// ---------------- GEMM  H = X @ W  (M=50000, K=128, N=128) + L/R epilogue ---
// block: 256 threads, tile 64 rows x 128 cols; thread = 8 rows x 4 cols
__global__ void gemm_lr_kernel(const float* __restrict__ X,
                               const float* __restrict__ W,
                               const float* __restrict__ attl,
                               const float* __restrict__ attr,
                               float* __restrict__ H,
                               float* __restrict__ Lo,
                               float* __restrict__ Ro) {
    __shared__ float Xs[64][64];    // 16 KB
    __shared__ float Ws[64][128];   // 32 KB  (total 48 KB)
    const int tid = threadIdx.x;
    const int tx  = tid & 31;       // lane -> col group
    const int ty  = tid >> 5;       // warp -> row group of 8
    const int row0 = blockIdx.x * 64;

    float acc[8][4];
#pragma unroll
    for (int i = 0; i < 8; i++)
#pragma unroll
        for (int j = 0; j < 4; j++) acc[i][j] = 0.f;

    for (int kc = 0; kc < 2; kc++) {
        // load X tile 64x64
#pragma unroll
        for (int v = 0; v < 4; v++) {
            int li = (tid + v * 256) * 4;
            int r = li >> 6, k = li & 63;
            int row = row0 + r;
            float4 val = make_float4(0.f, 0.f, 0.f, 0.f);
            if (row < NN) val = *(const float4*)(X + (size_t)row * HIDD + kc * 64 + k);
            *(float4*)(&Xs[r][k]) = val;
        }
        // load W tile 64x128
#pragma unroll
        for (int v = 0; v < 8; v++) {
            int li = (tid + v * 256) * 4;
            int k = li >> 7, c = li & 127;
            *(float4*)(&Ws[k][c]) = *(const float4*)(W + (size_t)(kc * 64 + k) * HIDD + c);
        }
        __syncthreads();
#pragma unroll 8
        for (int kk = 0; kk < 64; kk++) {
            float wv[4];
#pragma unroll
            for (int j = 0; j < 4; j++) wv[j] = Ws[kk][tx + 32 * j];
#pragma unroll
            for (int i = 0; i < 8; i++) {
                float xv = Xs[ty * 8 + i][kk];
#pragma unroll
                for (int j = 0; j < 4; j++) acc[i][j] = fmaf(xv, wv[j], acc[i][j]);
            }
        }
        __syncthreads();
    }

    float alv[4], arv[4];
#pragma unroll
    for (int j = 0; j < 4; j++) { alv[j] = attl[tx + 32 * j]; arv[j] = attr[tx + 32 * j]; }

#pragma unroll
    for (int i = 0; i < 8; i++) {
        int row = row0 + ty * 8 + i;
        if (row < NN) {
            float ls = 0.f, rs = 0.f;
#pragma unroll
            for (int j = 0; j < 4; j++) {
                H[(size_t)row * HIDD + tx + 32 * j] = acc[i][j];
                ls = fmaf(acc[i][j], alv[j], ls);
                rs = fmaf(acc[i][j], arv[j], rs);
            }
#pragma unroll
            for (int o = 16; o; o >>= 1) {
                ls += __shfl_xor_sync(0xFFFFFFFFu, ls, o);
                rs += __shfl_xor_sync(0xFFFFFFFFu, rs, o);
            }
            if (tx == 0) { Lo[row] = ls; Ro[row] = rs; }
        }
    }
}

// ---------------- per-layer init: zero aggregation buffer, reset softmax state
__global__ void init_kernel(float* __restrict__ out) {
    int i = blockIdx.x * blockDim.x + threadIdx.x;
    if (i < NN * HIDD) out[i] = 0.f;
    if (i < NN) { g_amax[i] = AMAX_INIT; g_denom[i] = 0.f; }
}

// ---------------- per-edge: alpha = (L[s]+R[d]) * sigmoid(h[s].h[d]); atomicMax
__global__ void edge_alpha_kernel(const float* __restrict__ H,
                                  const int* __restrict__ ei) {
    int e = (blockIdx.x * blockDim.x + threadIdx.x) >> 5;
    int lane = threadIdx.x & 31;
    if (e >= EP) return;
    int s = (e < EE) ? ei[e]      : (e - EE);
    int d = (e < EE) ? ei[EE + e] : (e - EE);
    float4 a = ((const float4*)(H + (size_t)s * HIDD))[lane];
    float4 b = ((const float4*)(H + (size_t)d * HIDD))[lane];
    float dot = a.x * b.x + a.y * b.y + a.z * b.z + a.w * b.w;
#pragma unroll
    for (int o = 16; o; o >>= 1) dot += __shfl_xor_sync(0xFFFFFFFFu, dot, o);
    if (lane == 0) {
        float al = g_L[s] + g_R[d];
        al = al * (1.f / (1.f + expf(-dot)));   // MX gating
        g_alpha[e] = al;
        atomicMax(&g_amax[d], f2o(al));
    }
}

// ---------------- per-edge: ea = exp(alpha - amax[d]); denom += ea ----------
__global__ void edge_exp_kernel(const int* __restrict__ ei) {
    int e = blockIdx.x * blockDim.x + threadIdx.x;
    if (e >= EP) return;
    int d = (e < EE) ? ei[EE + e] : (e - EE);
    float m = o2f(g_amax[d]);
    float ea = expf(g_alpha[e] - m);
    g_alpha[e] = ea;
    atomicAdd(&g_denom[d], ea);
}

// ---------------- per-edge: out[d] += h[s] * (ea / (denom[d]+eps)) ----------
__global__ void edge_agg_kernel(const float* __restrict__ H,
                                const int* __restrict__ ei,
                                float* __restrict__ out) {
    int e = (blockIdx.x * blockDim.x + threadIdx.x) >> 5;
    int lane = threadIdx.x & 31;
    if (e >= EP) return;
    int s = (e < EE) ? ei[e]      : (e - EE);
    int d = (e < EE) ? ei[EE + e] : (e - EE);
    float w = g_alpha[e] / (g_denom[d] + 1e-16f);
    float4 hv = ((const float4*)(H + (size_t)s * HIDD))[lane];
    float* o = out + (size_t)d * HIDD + lane * 4;
    atomicAdd(o + 0, hv.x * w);
    atomicAdd(o + 1, hv.y * w);
    atomicAdd(o + 2, hv.z * w);
    atomicAdd(o + 3, hv.w * w);
}

// ---------------- bias (+ optional relu) ------------------------------------
__global__ void bias_act_kernel(float* __restrict__ h, const float* __restrict__ b,
                                int do_relu) {
    int i = blockIdx.x * blockDim.x + threadIdx.x;
    if (i >= NN * HIDD) return;
    float v = h[i] + b[i & (HIDD - 1)];
    if (do_relu) v = fmaxf(v, 0.f);
    h[i] = v;
}

// ---------------- classifier decomposition: P = h@Wc[:128], Q = h@Wc[128:] --
__global__ void node_pq_kernel(const float* __restrict__ H,
                               const float* __restrict__ Wc) {
    int lane  = threadIdx.x & 31;
    int warp  = (blockIdx.x * blockDim.x + threadIdx.x) >> 5;
    int nwarp = (gridDim.x * blockDim.x) >> 5;
    float wt[4][4], wb[4][4];
#pragma unroll
    for (int i = 0; i < 4; i++)
#pragma unroll
        for (int o = 0; o < 4; o++) {
            wt[i][o] = Wc[(lane * 4 + i) * OUTD + o];
            wb[i][o] = Wc[(HIDD + lane * 4 + i) * OUTD + o];
        }
    for (int n = warp; n < NN; n += nwarp) {
        float4 hv = ((const float4*)(H + (size_t)n * HIDD))[lane];
        float h4[4] = {hv.x, hv.y, hv.z, hv.w};
        float p[4] = {0.f, 0.f, 0.f, 0.f}, q[4] = {0.f, 0.f, 0.f, 0.f};
#pragma unroll
        for (int i = 0; i < 4; i++)
#pragma unroll
            for (int o = 0; o < 4; o++) {
                p[o] = fmaf(h4[i], wt[i][o], p[o]);
                q[o] = fmaf(h4[i], wb[i][o], q[o]);
            }
#pragma unroll
        for (int o = 0; o < 4; o++)
#pragma unroll
            for (int off = 16; off; off >>= 1) {
                p[o] += __shfl_xor_sync(0xFFFFFFFFu, p[o], off);
                q[o] += __shfl_xor_sync(0xFFFFFFFFu, q[o], off);
            }
        if (lane == 0) {
            *(float4*)(g_P + (size_t)n * OUTD) = make_float4(p[0], p[1], p[2], p[3]);
            *(float4*)(g_Q + (size_t)n * OUTD) = make_float4(q[0], q[1], q[2], q[3]);
        }
    }
}

// ---------------- final per-edge output: out[e] = P[row] + Q[col] + bc ------
__global__ void edge_out_kernel(const int* __restrict__ ei,
                                const float* __restrict__ bc,
                                float* __restrict__ out) {
    int e = blockIdx.x * blockDim.x + threadIdx.x;
    if (e >= EE) return;
    int r = ei[e], c = ei[EE + e];
    float4 p = *(const float4*)(g_P + (size_t)r * OUTD);
    float4 q = *(const float4*)(g_Q + (size_t)c * OUTD);
    float b0 = bc[0], b1 = bc[1], b2 = bc[2], b3 = bc[3];
    *(float4*)(out + (size_t)e * OUTD) =
        make_float4(p.x + q.x + b0, p.y + q.y + b1, p.z + q.z + b2, p.w + q.w + b3);
}

// ---------------- launcher ---------------------------------------------------
extern "C" void kernel_launch(void* const* d_in, const int* in_sizes, int n_in,
                              void* d_out, int out_size) {
    const float* x   = (const float*)d_in[0];
    const int*   ei  = (const int*)d_in[1];
    const float* W1  = (const float*)d_in[2];
    const float* al1 = (const float*)d_in[3];
    const float* ar1 = (const float*)d_in[4];
    const float* b1  = (const float*)d_in[5];
    const float* W2  = (const float*)d_in[6];
    const float* al2 = (const float*)d_in[7];
    const float* ar2 = (const float*)d_in[8];
    const float* b2  = (const float*)d_in[9];
    const float* Wc  = (const float*)d_in[10];
    const float* bc  = (const float*)d_in[11];
    float* out = (float*)d_out;

    float *hA, *hB, *L, *R;
    cudaGetSymbolAddress((void**)&hA, g_hA);
    cudaGetSymbolAddress((void**)&hB, g_hB);
    cudaGetSymbolAddress((void**)&L,  g_L);
    cudaGetSymbolAddress((void**)&R,  g_R);

    const int TB = 256;
    const int gGemm = (NN + 63) / 64;                 // 782
    const int gInit = (NN * HIDD + TB - 1) / TB;      // 25000
    const int gEdgeW = (EP * 32 + TB - 1) / TB;       // warp-per-edge: 106250
    const int gEdgeT = (EP + TB - 1) / TB;            // 3321
    const int gEOut  = (EE + TB - 1) / TB;            // 3125

    // ---- layer 1 ----
    gemm_lr_kernel<<<gGemm, TB>>>(x, W1, al1, ar1, hA, L, R);
    init_kernel<<<gInit, TB>>>(hB);
    edge_alpha_kernel<<<gEdgeW, TB>>>(hA, ei);
    edge_exp_kernel<<<gEdgeT, TB>>>(ei);
    edge_agg_kernel<<<gEdgeW, TB>>>(hA, ei, hB);
    bias_act_kernel<<<gInit, TB>>>(hB, b1, 1);

    // ---- layer 2 ----
    gemm_lr_kernel<<<gGemm, TB>>>(hB, W2, al2, ar2, hA, L, R);
    init_kernel<<<gInit, TB>>>(hB);
    edge_alpha_kernel<<<gEdgeW, TB>>>(hA, ei);
    edge_exp_kernel<<<gEdgeT, TB>>>(ei);
    edge_agg_kernel<<<gEdgeW, TB>>>(hA, ei, hB);
    bias_act_kernel<<<gInit, TB>>>(hB, b2, 0);

    // ---- edge classifier (decomposed) ----
    node_pq_kernel<<<1184, TB>>>(hB, Wc);
    edge_out_kernel<<<gEOut, TB>>>(ei, bc, out);
}

// round 3
// speedup vs baseline: 2.5275x; 2.5275x over previous
#include <cuda_runtime.h>

#define NN   50000
#define EE   800000
#define HIDD 128
#define OUTD 4

// ---------------- scratch (static device globals; no runtime allocation) ----
__device__ float g_hA[(size_t)NN * HIDD];   // transformed features (gather source)
__device__ float g_hB[(size_t)NN * HIDD];   // aggregated output
__device__ float g_L[NN];
__device__ float g_R[NN];
__device__ int   g_cnt[NN];
__device__ int   g_cursor[NN];
__device__ int   g_start[NN + 1];
__device__ int   g_csrc[EE];                // edge sources sorted by destination
__device__ float g_P[NN * OUTD];
__device__ float g_Q[NN * OUTD];

// ---------------- GEMM  H = X @ W  (M=50000, K=128, N=128) + L/R epilogue ---
__global__ void gemm_lr_kernel(const float* __restrict__ X,
                               const float* __restrict__ W,
                               const float* __restrict__ attl,
                               const float* __restrict__ attr,
                               float* __restrict__ H,
                               float* __restrict__ Lo,
                               float* __restrict__ Ro) {
    __shared__ float Xs[64][64];
    __shared__ float Ws[64][128];
    const int tid = threadIdx.x;
    const int tx  = tid & 31;
    const int ty  = tid >> 5;
    const int row0 = blockIdx.x * 64;

    float acc[8][4];
#pragma unroll
    for (int i = 0; i < 8; i++)
#pragma unroll
        for (int j = 0; j < 4; j++) acc[i][j] = 0.f;

    for (int kc = 0; kc < 2; kc++) {
#pragma unroll
        for (int v = 0; v < 4; v++) {
            int li = (tid + v * 256) * 4;
            int r = li >> 6, k = li & 63;
            int row = row0 + r;
            float4 val = make_float4(0.f, 0.f, 0.f, 0.f);
            if (row < NN) val = *(const float4*)(X + (size_t)row * HIDD + kc * 64 + k);
            *(float4*)(&Xs[r][k]) = val;
        }
#pragma unroll
        for (int v = 0; v < 8; v++) {
            int li = (tid + v * 256) * 4;
            int k = li >> 7, c = li & 127;
            *(float4*)(&Ws[k][c]) = *(const float4*)(W + (size_t)(kc * 64 + k) * HIDD + c);
        }
        __syncthreads();
#pragma unroll 8
        for (int kk = 0; kk < 64; kk++) {
            float wv[4];
#pragma unroll
            for (int j = 0; j < 4; j++) wv[j] = Ws[kk][tx + 32 * j];
#pragma unroll
            for (int i = 0; i < 8; i++) {
                float xv = Xs[ty * 8 + i][kk];
#pragma unroll
                for (int j = 0; j < 4; j++) acc[i][j] = fmaf(xv, wv[j], acc[i][j]);
            }
        }
        __syncthreads();
    }

    float alv[4], arv[4];
#pragma unroll
    for (int j = 0; j < 4; j++) { alv[j] = attl[tx + 32 * j]; arv[j] = attr[tx + 32 * j]; }

#pragma unroll
    for (int i = 0; i < 8; i++) {
        int row = row0 + ty * 8 + i;
        if (row < NN) {
            float ls = 0.f, rs = 0.f;
#pragma unroll
            for (int j = 0; j < 4; j++) {
                H[(size_t)row * HIDD + tx + 32 * j] = acc[i][j];
                ls = fmaf(acc[i][j], alv[j], ls);
                rs = fmaf(acc[i][j], arv[j], rs);
            }
#pragma unroll
            for (int o = 16; o; o >>= 1) {
                ls += __shfl_xor_sync(0xFFFFFFFFu, ls, o);
                rs += __shfl_xor_sync(0xFFFFFFFFu, rs, o);
            }
            if (tx == 0) { Lo[row] = ls; Ro[row] = rs; }
        }
    }
}

// ---------------- CSR build --------------------------------------------------
__global__ void csr_zero_kernel() {
    int i = blockIdx.x * blockDim.x + threadIdx.x;
    if (i < NN) { g_cnt[i] = 0; g_cursor[i] = 0; }
}

__global__ void csr_count_kernel(const int* __restrict__ ei) {
    int e = blockIdx.x * blockDim.x + threadIdx.x;
    if (e >= EE) return;
    atomicAdd(&g_cnt[ei[EE + e]], 1);
}

// single-block exclusive scan over g_cnt -> g_start (50K elements)
__global__ void csr_scan_kernel() {
    __shared__ int wsum[32];
    __shared__ int carry;
    const int tid = threadIdx.x, lane = tid & 31, wid = tid >> 5;
    if (tid == 0) carry = 0;
    __syncthreads();
    for (int base = 0; base < NN; base += 1024) {
        int i = base + tid;
        int v = (i < NN) ? g_cnt[i] : 0;
        int x = v;
#pragma unroll
        for (int o = 1; o < 32; o <<= 1) {
            int y = __shfl_up_sync(0xFFFFFFFFu, x, o);
            if (lane >= o) x += y;
        }
        if (lane == 31) wsum[wid] = x;
        __syncthreads();
        if (wid == 0) {
            int s = wsum[lane];
#pragma unroll
            for (int o = 1; o < 32; o <<= 1) {
                int y = __shfl_up_sync(0xFFFFFFFFu, s, o);
                if (lane >= o) s += y;
            }
            wsum[lane] = s;
        }
        __syncthreads();
        int pre = (wid > 0 ? wsum[wid - 1] : 0) + carry;
        if (i < NN) g_start[i] = pre + x - v;
        int total = wsum[31];
        __syncthreads();
        if (tid == 0) carry += total;
        __syncthreads();
    }
    if (tid == 0) g_start[NN] = carry;
}

__global__ void csr_scatter_kernel(const int* __restrict__ ei) {
    int e = blockIdx.x * blockDim.x + threadIdx.x;
    if (e >= EE) return;
    int s = ei[e], d = ei[EE + e];
    int pos = g_start[d] + atomicAdd(&g_cursor[d], 1);
    g_csrc[pos] = s;
}

// ---------------- fused attention: warp per destination node ----------------
// online softmax over {self-loop} + CSR incoming edges; zero atomics
__global__ void attn_kernel(const float* __restrict__ H,
                            const float* __restrict__ bias,
                            int do_relu,
                            float* __restrict__ out) {
    int n    = (blockIdx.x * blockDim.x + threadIdx.x) >> 5;
    int lane = threadIdx.x & 31;
    if (n >= NN) return;

    float4 hd = ((const float4*)(H + (size_t)n * HIDD))[lane];
    float Rd = g_R[n];
    float Ln = g_L[n];

    // self-loop first
    float dp = hd.x * hd.x + hd.y * hd.y + hd.z * hd.z + hd.w * hd.w;
#pragma unroll
    for (int o = 16; o; o >>= 1) dp += __shfl_xor_sync(0xFFFFFFFFu, dp, o);
    float m = (Ln + Rd) * (1.f / (1.f + expf(-dp)));
    float den = 1.f;
    float4 acc = hd;

    const int beg = g_start[n], end = g_start[n + 1];
    int p = beg;
    int s_n = 0; float4 hs_n = make_float4(0.f, 0.f, 0.f, 0.f); float Ls_n = 0.f;
    if (p < end) {
        s_n  = g_csrc[p];
        hs_n = ((const float4*)(H + (size_t)s_n * HIDD))[lane];
        Ls_n = g_L[s_n];
    }
    for (; p < end; p++) {
        float4 hs = hs_n; float Ls = Ls_n;
        if (p + 1 < end) {                       // prefetch next edge
            int s2 = g_csrc[p + 1];
            hs_n = ((const float4*)(H + (size_t)s2 * HIDD))[lane];
            Ls_n = g_L[s2];
        }
        float d2 = hs.x * hd.x + hs.y * hd.y + hs.z * hd.z + hs.w * hd.w;
#pragma unroll
        for (int o = 16; o; o >>= 1) d2 += __shfl_xor_sync(0xFFFFFFFFu, d2, o);
        float al = (Ls + Rd) * (1.f / (1.f + expf(-d2)));
        if (al > m) {                            // warp-uniform branch
            float c = expf(m - al);
            den *= c;
            acc.x *= c; acc.y *= c; acc.z *= c; acc.w *= c;
            m = al;
        }
        float w = expf(al - m);
        den += w;
        acc.x = fmaf(w, hs.x, acc.x);
        acc.y = fmaf(w, hs.y, acc.y);
        acc.z = fmaf(w, hs.z, acc.z);
        acc.w = fmaf(w, hs.w, acc.w);
    }

    float inv = 1.f / (den + 1e-16f);
    float4 b = ((const float4*)bias)[lane];
    float4 r;
    r.x = fmaf(acc.x, inv, b.x);
    r.y = fmaf(acc.y, inv, b.y);
    r.z = fmaf(acc.z, inv, b.z);
    r.w = fmaf(acc.w, inv, b.w);
    if (do_relu) {
        r.x = fmaxf(r.x, 0.f); r.y = fmaxf(r.y, 0.f);
        r.z = fmaxf(r.z, 0.f); r.w = fmaxf(r.w, 0.f);
    }
    ((float4*)(out + (size_t)n * HIDD))[lane] = r;
}

// ---------------- classifier decomposition: P = h@Wc[:128], Q = h@Wc[128:] --
__global__ void node_pq_kernel(const float* __restrict__ H,
                               const float* __restrict__ Wc) {
    int lane  = threadIdx.x & 31;
    int warp  = (blockIdx.x * blockDim.x + threadIdx.x) >> 5;
    int nwarp = (gridDim.x * blockDim.x) >> 5;
    float wt[4][4], wb[4][4];
#pragma unroll
    for (int i = 0; i < 4; i++)
#pragma unroll
        for (int o = 0; o < 4; o++) {
            wt[i][o] = Wc[(lane * 4 + i) * OUTD + o];
            wb[i][o] = Wc[(HIDD + lane * 4 + i) * OUTD + o];
        }
    for (int n = warp; n < NN; n += nwarp) {
        float4 hv = ((const float4*)(H + (size_t)n * HIDD))[lane];
        float h4[4] = {hv.x, hv.y, hv.z, hv.w};
        float pv[4] = {0.f, 0.f, 0.f, 0.f}, qv[4] = {0.f, 0.f, 0.f, 0.f};
#pragma unroll
        for (int i = 0; i < 4; i++)
#pragma unroll
            for (int o = 0; o < 4; o++) {
                pv[o] = fmaf(h4[i], wt[i][o], pv[o]);
                qv[o] = fmaf(h4[i], wb[i][o], qv[o]);
            }
#pragma unroll
        for (int o = 0; o < 4; o++)
#pragma unroll
            for (int off = 16; off; off >>= 1) {
                pv[o] += __shfl_xor_sync(0xFFFFFFFFu, pv[o], off);
                qv[o] += __shfl_xor_sync(0xFFFFFFFFu, qv[o], off);
            }
        if (lane == 0) {
            *(float4*)(g_P + (size_t)n * OUTD) = make_float4(pv[0], pv[1], pv[2], pv[3]);
            *(float4*)(g_Q + (size_t)n * OUTD) = make_float4(qv[0], qv[1], qv[2], qv[3]);
        }
    }
}

// ---------------- final per-edge output: out[e] = P[row] + Q[col] + bc ------
__global__ void edge_out_kernel(const int* __restrict__ ei,
                                const float* __restrict__ bc,
                                float* __restrict__ out) {
    int e = blockIdx.x * blockDim.x + threadIdx.x;
    if (e >= EE) return;
    int r = ei[e], c = ei[EE + e];
    float4 p = *(const float4*)(g_P + (size_t)r * OUTD);
    float4 q = *(const float4*)(g_Q + (size_t)c * OUTD);
    float b0 = bc[0], b1 = bc[1], b2 = bc[2], b3 = bc[3];
    *(float4*)(out + (size_t)e * OUTD) =
        make_float4(p.x + q.x + b0, p.y + q.y + b1, p.z + q.z + b2, p.w + q.w + b3);
}

// ---------------- launcher ---------------------------------------------------
extern "C" void kernel_launch(void* const* d_in, const int* in_sizes, int n_in,
                              void* d_out, int out_size) {
    const float* x   = (const float*)d_in[0];
    const int*   ei  = (const int*)d_in[1];
    const float* W1  = (const float*)d_in[2];
    const float* al1 = (const float*)d_in[3];
    const float* ar1 = (const float*)d_in[4];
    const float* b1  = (const float*)d_in[5];
    const float* W2  = (const float*)d_in[6];
    const float* al2 = (const float*)d_in[7];
    const float* ar2 = (const float*)d_in[8];
    const float* b2  = (const float*)d_in[9];
    const float* Wc  = (const float*)d_in[10];
    const float* bc  = (const float*)d_in[11];
    float* out = (float*)d_out;

    float *hA, *hB, *L, *R;
    cudaGetSymbolAddress((void**)&hA, g_hA);
    cudaGetSymbolAddress((void**)&hB, g_hB);
    cudaGetSymbolAddress((void**)&L,  g_L);
    cudaGetSymbolAddress((void**)&R,  g_R);

    const int TB = 256;
    const int gGemm = (NN + 63) / 64;
    const int gNode = (NN + TB - 1) / TB;             // 196
    const int gEdge = (EE + TB - 1) / TB;             // 3125
    const int gAttn = (NN * 32 + TB - 1) / TB;        // 6250 (warp per node)

    // ---- CSR build (by destination), reused by both layers ----
    csr_zero_kernel<<<gNode, TB>>>();
    csr_count_kernel<<<gEdge, TB>>>(ei);
    csr_scan_kernel<<<1, 1024>>>();
    csr_scatter_kernel<<<gEdge, TB>>>(ei);

    // ---- layer 1 ----
    gemm_lr_kernel<<<gGemm, TB>>>(x, W1, al1, ar1, hA, L, R);
    attn_kernel<<<gAttn, TB>>>(hA, b1, 1, hB);

    // ---- layer 2 ----
    gemm_lr_kernel<<<gGemm, TB>>>(hB, W2, al2, ar2, hA, L, R);
    attn_kernel<<<gAttn, TB>>>(hA, b2, 0, hB);

    // ---- edge classifier (decomposed) ----
    node_pq_kernel<<<1184, TB>>>(hB, Wc);
    edge_out_kernel<<<gEdge, TB>>>(ei, bc, out);
}